// round 12
// baseline (speedup 1.0000x reference)
#include <cuda_runtime.h>
#include <cuda_bf16.h>
#include <cuda_fp16.h>
#include <cstdint>

// Problem constants (fixed by setup_inputs)
#define B_  4
#define T_  1024
#define C_  1024
#define H_  16
#define DH  64
#define MAXREL 32

// W-scale: keeps relu(..)+1e-6 weights inside fp16 normal range.
#define WSCALE 256.0f
#define WSCALE_INV (1.0f / 256.0f)

// Scratch (allocation-free rule: __device__ globals)
__device__ __half  g_x2 [B_*T_*C_];
__device__ __half  g_w2q[C_*C_], g_w2k[C_*C_], g_w2v[C_*C_], g_w2o[C_*C_];
__device__ __half  g_ath[B_*T_*C_];
__device__ __half  g_Vth[B_*H_*DH*T_];         // V half, [B,H,D,T]
__device__ unsigned g_Qhi[B_*H_*T_*DH/2], g_Qlo[B_*H_*T_*DH/2];  // bf16x2 pairs
__device__ unsigned g_Khi[B_*H_*T_*DH/2], g_Klo[B_*H_*T_*DH/2];

__device__ __forceinline__ uint32_t smem_u32(const void* p) {
    uint32_t a;
    asm("{ .reg .u64 t; cvta.to.shared.u64 t, %1; cvt.u32.u64 %0, t; }"
        : "=r"(a) : "l"(p));
    return a;
}

#define MMA_BF16(acc, a, b0, b1)                                              \
    asm volatile(                                                             \
        "mma.sync.aligned.m16n8k16.row.col.f32.bf16.bf16.f32 "                \
        "{%0,%1,%2,%3}, {%4,%5,%6,%7}, {%8,%9}, {%0,%1,%2,%3};"               \
        : "+f"(acc[0]), "+f"(acc[1]), "+f"(acc[2]), "+f"(acc[3])              \
        : "r"(a[0]), "r"(a[1]), "r"(a[2]), "r"(a[3]), "r"(b0), "r"(b1))

#define MMA_FP16(acc, a, b0, b1)                                              \
    asm volatile(                                                             \
        "mma.sync.aligned.m16n8k16.row.col.f32.f16.f16.f32 "                  \
        "{%0,%1,%2,%3}, {%4,%5,%6,%7}, {%8,%9}, {%0,%1,%2,%3};"               \
        : "+f"(acc[0]), "+f"(acc[1]), "+f"(acc[2]), "+f"(acc[3])              \
        : "r"(a[0]), "r"(a[1]), "r"(a[2]), "r"(a[3]), "r"(b0), "r"(b1))

#define LDSM_X4(r0, r1, r2, r3, addr)                                         \
    asm volatile("ldmatrix.sync.aligned.m8n8.x4.shared.b16 {%0,%1,%2,%3}, [%4];" \
        : "=r"(r0), "=r"(r1), "=r"(r2), "=r"(r3) : "r"(addr))

#define CP_ASYNC16(saddr, gptr)                                               \
    asm volatile("cp.async.cg.shared.global [%0], [%1], 16;"                  \
                 :: "r"(saddr), "l"(gptr) : "memory")
#define CP_COMMIT()      asm volatile("cp.async.commit_group;" ::: "memory")
#define CP_WAIT(n)       asm volatile("cp.async.wait_group %0;" :: "n"(n) : "memory")

// ---------------------------------------------------------------------------
// f32 -> half conversion
// ---------------------------------------------------------------------------
__global__ void cvt_half4(const float* __restrict__ i0, __half* __restrict__ o0,
                          const float* __restrict__ i1, __half* __restrict__ o1,
                          const float* __restrict__ i2, __half* __restrict__ o2,
                          const float* __restrict__ i3, __half* __restrict__ o3,
                          int n)
{
    const float* in  = blockIdx.y == 0 ? i0 : blockIdx.y == 1 ? i1
                     : blockIdx.y == 2 ? i2 : i3;
    __half* out      = blockIdx.y == 0 ? o0 : blockIdx.y == 1 ? o1
                     : blockIdx.y == 2 ? o2 : o3;
    const int i = (blockIdx.x * blockDim.x + threadIdx.x) * 8;
    if (i >= n) return;
    float4 v0 = *(const float4*)(in + i);
    float4 v1 = *(const float4*)(in + i + 4);
    __half2 h[4] = {__floats2half2_rn(v0.x, v0.y), __floats2half2_rn(v0.z, v0.w),
                    __floats2half2_rn(v1.x, v1.y), __floats2half2_rn(v1.z, v1.w)};
    *(uint4*)(out + i) = *(uint4*)h;
}
__global__ void cvt_half(const float* __restrict__ in, __half* __restrict__ out,
                         int n)
{
    const int i = (blockIdx.x * blockDim.x + threadIdx.x) * 8;
    if (i >= n) return;
    float4 v0 = *(const float4*)(in + i);
    float4 v1 = *(const float4*)(in + i + 4);
    __half2 h[4] = {__floats2half2_rn(v0.x, v0.y), __floats2half2_rn(v0.z, v0.w),
                    __floats2half2_rn(v1.x, v1.y), __floats2half2_rn(v1.z, v1.w)};
    *(uint4*)(out + i) = *(uint4*)h;
}

// ---------------------------------------------------------------------------
// fp16 GEMM, BK=64, 3-stage cp.async, ldmatrix. 16 k-iters, 64 HMMA/iter/warp.
// FUSED=1: QKV in one launch, grid (24,32); which = bx>>3 selects W/bias/out.
// FUSED=0: output GEMM, grid (8,32), fp32 C.
// smem: 3 stages x (A+B) x 128 rows x 36 u32 stride = 110592 B.
// ---------------------------------------------------------------------------
#define GST   36
#define TILE_U (128 * GST)
#define GEMM_SMEM (3 * 2 * TILE_U * 4)   // 110592 B

__device__ __forceinline__ void store_hilo(unsigned* Phi, unsigned* Plo, size_t off,
                                           float x, float y) {
    __nv_bfloat16 hx = __float2bfloat16(x), hy = __float2bfloat16(y);
    __nv_bfloat162 h2(hx, hy);
    __nv_bfloat162 l2(__float2bfloat16(x - __bfloat162float(hx)),
                      __float2bfloat16(y - __bfloat162float(hy)));
    Phi[off] = *(unsigned*)&h2;
    Plo[off] = *(unsigned*)&l2;
}

template<int FUSED>
__global__ void __launch_bounds__(256, 2)
gemm_h3(const __half* __restrict__ A,
        const __half* __restrict__ W0, const __half* __restrict__ W1,
        const __half* __restrict__ W2,
        const float* __restrict__ b0, const float* __restrict__ b1,
        const float* __restrict__ b2,
        float* __restrict__ C,
        unsigned* __restrict__ qhi, unsigned* __restrict__ qlo,
        unsigned* __restrict__ khi, unsigned* __restrict__ klo,
        __half* __restrict__ Vh)
{
    const int K = 1024, N = 1024;
    extern __shared__ unsigned sm[];

    const int which = FUSED ? ((int)blockIdx.x >> 3) : 0;
    const __half* W = FUSED ? (which == 0 ? W0 : which == 1 ? W1 : W2) : W0;
    const float* bias = FUSED ? (which == 0 ? b0 : which == 1 ? b1 : b2) : b0;

    const int t = threadIdx.x;
    const int lane = t & 31, warp = t >> 5;
    const int wm = warp >> 2, wn = warp & 3;
    const int m0 = blockIdx.y * 128, n0 = ((int)blockIdx.x & 7) * 128;

    // ldmatrix lane decomposition
    const int lrow = lane & 7;
    const int agrp_r = ((lane >> 3) & 1) * 8;
    const int agrp_c = ((lane >> 4) & 1) * 4;
    const int bgrp_r = ((lane >> 4) & 1) * 8;
    const int bgrp_c = ((lane >> 3) & 1) * 4;

    const int r   = t >> 1;
    const int seg = t & 1;
    const __half* Ap = A + (size_t)(m0 + r) * K + seg * 32;
    const __half* Wp = W + (size_t)(n0 + r) * K + seg * 32;
    const uint32_t smbase = smem_u32(sm);
    const uint32_t dstA = smbase + (r * GST + seg * 16) * 4;
    const uint32_t dstB = dstA + TILE_U * 4;

    auto issue = [&](int kt) {
        const uint32_t sb = (kt % 3) * (2 * TILE_U * 4);
        const __half* a = Ap + kt * 64;
        const __half* b = Wp + kt * 64;
        CP_ASYNC16(dstA + sb,      a);
        CP_ASYNC16(dstA + sb + 16, a + 8);
        CP_ASYNC16(dstA + sb + 32, a + 16);
        CP_ASYNC16(dstA + sb + 48, a + 24);
        CP_ASYNC16(dstB + sb,      b);
        CP_ASYNC16(dstB + sb + 16, b + 8);
        CP_ASYNC16(dstB + sb + 32, b + 16);
        CP_ASYNC16(dstB + sb + 48, b + 24);
        CP_COMMIT();
    };

    float acc[4][4][4];
#pragma unroll
    for (int i = 0; i < 4; i++)
#pragma unroll
        for (int j = 0; j < 4; j++)
#pragma unroll
            for (int x = 0; x < 4; x++) acc[i][j][x] = 0.f;

    issue(0);
    issue(1);

    const int NKT = K / 64;   // 16
    for (int kt = 0; kt < NKT; kt++) {
        CP_WAIT(1);
        __syncthreads();

        const uint32_t sa = smbase + (kt % 3) * 2 * TILE_U * 4;
        const uint32_t sb = sa + TILE_U * 4;
#pragma unroll
        for (int s = 0; s < 4; s++) {
            const int g0 = s * 8;
            unsigned af[4][4], bf[4][2];
#pragma unroll
            for (int mf = 0; mf < 4; mf++) {
                const int rr = wm * 64 + mf * 16 + agrp_r + lrow;
                LDSM_X4(af[mf][0], af[mf][1], af[mf][2], af[mf][3],
                        sa + (rr * GST + g0 + agrp_c) * 4);
            }
#pragma unroll
            for (int np = 0; np < 2; np++) {
                const int rr = wn * 32 + (np * 2) * 8 + bgrp_r + lrow;
                LDSM_X4(bf[np*2][0], bf[np*2][1], bf[np*2+1][0], bf[np*2+1][1],
                        sb + (rr * GST + g0 + bgrp_c) * 4);
            }
#pragma unroll
            for (int mf = 0; mf < 4; mf++)
#pragma unroll
                for (int nf = 0; nf < 4; nf++)
                    MMA_FP16(acc[mf][nf], af[mf], bf[nf][0], bf[nf][1]);
        }
        if (kt + 2 < NKT) issue(kt + 2);
    }

    // epilogue
#pragma unroll
    for (int nf = 0; nf < 4; nf++) {
        const int col = n0 + wn * 32 + nf * 8 + (lane & 3) * 2;
        const float bv0 = bias[col], bv1 = bias[col + 1];
#pragma unroll
        for (int mf = 0; mf < 4; mf++) {
            const int row = m0 + wm * 64 + mf * 16 + (lane >> 2);
            float2 v0 = make_float2(acc[mf][nf][0] + bv0, acc[mf][nf][1] + bv1);
            float2 v1 = make_float2(acc[mf][nf][2] + bv0, acc[mf][nf][3] + bv1);
            if (!FUSED) {
                *(float2*)(C + (size_t)row * N + col)       = v0;
                *(float2*)(C + (size_t)(row + 8) * N + col) = v1;
            } else if (which < 2) {
                unsigned* Phi = which == 0 ? qhi : khi;
                unsigned* Plo = which == 0 ? qlo : klo;
                const int h = col >> 6, d = col & 63, pr = d >> 1;
                const int bb = row >> 10, tt = row & 1023;
                const size_t off = ((((size_t)bb * H_ + h) * T_ + tt) * 32) + pr;
                store_hilo(Phi, Plo, off,          v0.x, v0.y);
                store_hilo(Phi, Plo, off + 8 * 32, v1.x, v1.y);
            } else {  // V half, transposed [B,H,D,T]
                const int h = col >> 6, d = col & 63;
                const int bb = row >> 10, tt = row & 1023;
                const size_t vb = (((size_t)bb * H_ + h) * DH + d) * T_ + tt;
                Vh[vb]          = __float2half(v0.x);
                Vh[vb + T_]     = __float2half(v0.y);
                Vh[vb + 8]      = __float2half(v1.x);
                Vh[vb + T_ + 8] = __float2half(v1.y);
            }
        }
    }
}

// ---------------------------------------------------------------------------
// Fused causal algebraic attention v4 (unchanged from round 11).
// ---------------------------------------------------------------------------
#define PST 36

__global__ void __launch_bounds__(256, 3)
attn_v4(const unsigned* __restrict__ Qhi, const unsigned* __restrict__ Qlo,
        const unsigned* __restrict__ Khi, const unsigned* __restrict__ Klo,
        const __half* __restrict__ Vtg, const float* __restrict__ rel_bias,
        __half* __restrict__ out)
{
    extern __shared__ unsigned sm[];
    unsigned* Qh_s = sm;
    unsigned* Ql_s = Qh_s + 64 * PST;
    unsigned* Kh_s = Ql_s + 64 * PST;
    unsigned* Kl_s = Kh_s + 64 * PST;
    unsigned* Vt_s = Kl_s + 64 * PST;
    unsigned* Ws_s = Vt_s + 64 * PST;
    float* bh   = (float*)(Ws_s + 64 * PST);
    float* rsum = bh + 64;

    const int qt = 15 - (int)blockIdx.x;
    const int h  = blockIdx.y;
    const int b  = blockIdx.z;
    const int t  = threadIdx.x;
    const int lane = t & 31, warp = t >> 5;
    const int wm = warp >> 1, wn = warp & 1;
    const int q0 = qt * 64;
    const int bhx = b * H_ + h;

    const int lrow = lane & 7;
    const int agrp_r = ((lane >> 3) & 1) * 8;
    const int agrp_c = ((lane >> 4) & 1) * 4;
    const int bgrp_r = ((lane >> 4) & 1) * 8;
    const int bgrp_c = ((lane >> 3) & 1) * 4;

    const uint32_t qh_b = smem_u32(Qh_s), ql_b = smem_u32(Ql_s);
    const uint32_t kh_b = smem_u32(Kh_s), kl_b = smem_u32(Kl_s);
    const uint32_t vt_b = smem_u32(Vt_s), ws_b = smem_u32(Ws_s);

    const int r4  = t >> 2;
    const int cp8 = (t & 3) * 8;

    {
        const size_t qoff = ((size_t)bhx * T_ + q0 + r4) * 32 + cp8;
        CP_ASYNC16(smem_u32(&Qh_s[r4 * PST + cp8]),     Qhi + qoff);
        CP_ASYNC16(smem_u32(&Qh_s[r4 * PST + cp8 + 4]), Qhi + qoff + 4);
        CP_ASYNC16(smem_u32(&Ql_s[r4 * PST + cp8]),     Qlo + qoff);
        CP_ASYNC16(smem_u32(&Ql_s[r4 * PST + cp8 + 4]), Qlo + qoff + 4);
        CP_COMMIT();
    }
    if (t < 2 * MAXREL - 1) bh[t] = rel_bias[t * H_ + h];
    if (t < 64) rsum[t] = 0.f;

    const unsigned* Khg = Khi + (size_t)bhx * T_ * 32;
    const unsigned* Klg = Klo + (size_t)bhx * T_ * 32;
    const __half*   Vbg = Vtg + (size_t)bhx * DH * T_;

    float oacc[4][4];
#pragma unroll
    for (int i = 0; i < 4; i++)
#pragma unroll
        for (int j = 0; j < 4; j++) oacc[i][j] = 0.f;
    float rp0 = 0.f, rp1 = 0.f;

    const int ar = wm * 16 + (lane >> 2);

    for (int kt = 0; kt <= qt; kt++) {
        const int k0 = kt * 64;
        __syncthreads();

        {
            const size_t koff = (size_t)(k0 + r4) * 32 + cp8;
            CP_ASYNC16(smem_u32(&Kh_s[r4 * PST + cp8]),     Khg + koff);
            CP_ASYNC16(smem_u32(&Kh_s[r4 * PST + cp8 + 4]), Khg + koff + 4);
            CP_ASYNC16(smem_u32(&Kl_s[r4 * PST + cp8]),     Klg + koff);
            CP_ASYNC16(smem_u32(&Kl_s[r4 * PST + cp8 + 4]), Klg + koff + 4);
            CP_COMMIT();
            const __half* vp = Vbg + (size_t)r4 * T_ + k0 + (t & 3) * 16;
            CP_ASYNC16(smem_u32(&Vt_s[r4 * PST + cp8]),     vp);
            CP_ASYNC16(smem_u32(&Vt_s[r4 * PST + cp8 + 4]), vp + 8);
            CP_COMMIT();
        }
        CP_WAIT(1);
        __syncthreads();

        float s[4][4];
#pragma unroll
        for (int i = 0; i < 4; i++)
#pragma unroll
            for (int j = 0; j < 4; j++) s[i][j] = 0.f;

#pragma unroll
        for (int st = 0; st < 4; st++) {
            const int g0 = st * 8;
            unsigned ah[4], al[4], bhf[4][2], blf[4][2];
            {
                const int rr = wm * 16 + agrp_r + lrow;
                LDSM_X4(ah[0], ah[1], ah[2], ah[3],
                        qh_b + (rr * PST + g0 + agrp_c) * 4);
                LDSM_X4(al[0], al[1], al[2], al[3],
                        ql_b + (rr * PST + g0 + agrp_c) * 4);
            }
#pragma unroll
            for (int np = 0; np < 2; np++) {
                const int rr = wn * 32 + (np * 2) * 8 + bgrp_r + lrow;
                LDSM_X4(bhf[np*2][0], bhf[np*2][1], bhf[np*2+1][0], bhf[np*2+1][1],
                        kh_b + (rr * PST + g0 + bgrp_c) * 4);
                LDSM_X4(blf[np*2][0], blf[np*2][1], blf[np*2+1][0], blf[np*2+1][1],
                        kl_b + (rr * PST + g0 + bgrp_c) * 4);
            }
#pragma unroll
            for (int nf = 0; nf < 4; nf++) {
                MMA_BF16(s[nf], ah, bhf[nf][0], bhf[nf][1]);
                MMA_BF16(s[nf], ah, blf[nf][0], blf[nf][1]);
                MMA_BF16(s[nf], al, bhf[nf][0], bhf[nf][1]);
            }
        }

        {
            const int qg0 = q0 + ar;
            const bool diag = (kt == qt);
#pragma unroll
            for (int nf = 0; nf < 4; nf++) {
                const int kg0 = k0 + wn * 32 + nf * 8 + (lane & 3) * 2;
                float w[4];
#pragma unroll
                for (int c = 0; c < 4; c++) {
                    const int qg = qg0 + (c >> 1) * 8;
                    const int kg = kg0 + (c & 1);
                    const int rel = kg - qg;
                    float wv = 0.f;
                    if (!diag || rel <= 0) {
                        const int u = max(rel + (MAXREL - 1), 0);
                        wv = fmaxf(fmaf(s[nf][c], 0.125f, bh[u]), 0.f) + 1e-6f;
                    }
                    w[c] = wv;
                }
                rp0 += w[0] + w[1];
                rp1 += w[2] + w[3];
                const int pc = wn * 16 + nf * 4 + (lane & 3);
                __half2 h0 = __floats2half2_rn(w[0] * WSCALE, w[1] * WSCALE);
                __half2 h1 = __floats2half2_rn(w[2] * WSCALE, w[3] * WSCALE);
                Ws_s[ar * PST + pc]       = *(unsigned*)&h0;
                Ws_s[(ar + 8) * PST + pc] = *(unsigned*)&h1;
            }
        }
        CP_WAIT(0);
        __syncthreads();

#pragma unroll
        for (int st = 0; st < 4; st++) {
            const int g0 = st * 8;
            unsigned a[4], bf[4][2];
            {
                const int rr = wm * 16 + agrp_r + lrow;
                LDSM_X4(a[0], a[1], a[2], a[3],
                        ws_b + (rr * PST + g0 + agrp_c) * 4);
            }
#pragma unroll
            for (int np = 0; np < 2; np++) {
                const int rr = wn * 32 + (np * 2) * 8 + bgrp_r + lrow;
                LDSM_X4(bf[np*2][0], bf[np*2][1], bf[np*2+1][0], bf[np*2+1][1],
                        vt_b + (rr * PST + g0 + bgrp_c) * 4);
            }
#pragma unroll
            for (int nf = 0; nf < 4; nf++)
                MMA_FP16(oacc[nf], a, bf[nf][0], bf[nf][1]);
        }
    }

    rp0 += __shfl_xor_sync(0xffffffffu, rp0, 1);
    rp0 += __shfl_xor_sync(0xffffffffu, rp0, 2);
    rp1 += __shfl_xor_sync(0xffffffffu, rp1, 1);
    rp1 += __shfl_xor_sync(0xffffffffu, rp1, 2);
    if ((lane & 3) == 0) {
        atomicAdd(&rsum[ar], rp0);
        atomicAdd(&rsum[ar + 8], rp1);
    }
    __syncthreads();

    const float inv0 = WSCALE_INV / (rsum[ar] + 1e-6f);
    const float inv1 = WSCALE_INV / (rsum[ar + 8] + 1e-6f);
#pragma unroll
    for (int nf = 0; nf < 4; nf++) {
        const int d = wn * 32 + nf * 8 + (lane & 3) * 2;
        __half* dst0 = out + (size_t)(b * T_ + q0 + ar) * C_ + h * DH + d;
        __half* dst1 = out + (size_t)(b * T_ + q0 + ar + 8) * C_ + h * DH + d;
        __half2 h0 = __floats2half2_rn(oacc[nf][0] * inv0, oacc[nf][1] * inv0);
        __half2 h1 = __floats2half2_rn(oacc[nf][2] * inv1, oacc[nf][3] * inv1);
        *(__half2*)dst0 = h0;
        *(__half2*)dst1 = h1;
    }
}

#define ATTN_SMEM ((6 * 64 * PST + 128) * 4)   // 55808 B

// ---------------------------------------------------------------------------
extern "C" void kernel_launch(void* const* d_in, const int* in_sizes, int n_in,
                              void* d_out, int out_size)
{
    const float* x   = (const float*)d_in[0];
    const float* Wq  = (const float*)d_in[2];
    const float* bq  = (const float*)d_in[3];
    const float* Wk  = (const float*)d_in[4];
    const float* bk  = (const float*)d_in[5];
    const float* Wv  = (const float*)d_in[6];
    const float* bv  = (const float*)d_in[7];
    const float* Wo  = (const float*)d_in[8];
    const float* bo  = (const float*)d_in[9];
    const float* rel = (const float*)d_in[10];

    __half *x2, *w2q, *w2k, *w2v, *w2o, *ath, *vth;
    unsigned *qhi, *qlo, *khi, *klo;
    cudaGetSymbolAddress((void**)&x2,  g_x2);
    cudaGetSymbolAddress((void**)&w2q, g_w2q);
    cudaGetSymbolAddress((void**)&w2k, g_w2k);
    cudaGetSymbolAddress((void**)&w2v, g_w2v);
    cudaGetSymbolAddress((void**)&w2o, g_w2o);
    cudaGetSymbolAddress((void**)&ath, g_ath);
    cudaGetSymbolAddress((void**)&vth, g_Vth);
    cudaGetSymbolAddress((void**)&qhi, g_Qhi);
    cudaGetSymbolAddress((void**)&qlo, g_Qlo);
    cudaGetSymbolAddress((void**)&khi, g_Khi);
    cudaGetSymbolAddress((void**)&klo, g_Klo);

    static int configured = 0;
    if (!configured) {
        cudaFuncSetAttribute(attn_v4, cudaFuncAttributeMaxDynamicSharedMemorySize,
                             ATTN_SMEM);
        cudaFuncSetAttribute(gemm_h3<0>, cudaFuncAttributeMaxDynamicSharedMemorySize,
                             GEMM_SMEM);
        cudaFuncSetAttribute(gemm_h3<1>, cudaFuncAttributeMaxDynamicSharedMemorySize,
                             GEMM_SMEM);
        configured = 1;
    }

    const int NX = B_ * T_ * C_, NW = C_ * C_;
    cvt_half4<<<dim3(NW / 2048, 4), 256>>>(Wq, w2q, Wk, w2k, Wv, w2v, Wo, w2o, NW);
    cvt_half<<<NX / 2048, 256>>>(x, x2, NX);

    // Fused Q/K/V projections: grid (24, 32); bx>>3 selects weight/output
    gemm_h3<1><<<dim3(24, 32), 256, GEMM_SMEM>>>(
        x2, w2q, w2k, w2v, bq, bk, bv, nullptr, qhi, qlo, khi, klo, vth);

    attn_v4<<<dim3(16, H_, B_), 256, ATTN_SMEM>>>(qhi, qlo, khi, klo, vth, rel, ath);

    gemm_h3<0><<<dim3(8, 32), 256, GEMM_SMEM>>>(
        ath, w2o, nullptr, nullptr, bo, nullptr, nullptr,
        (float*)d_out, nullptr, nullptr, nullptr, nullptr, nullptr);
}

// round 13
// speedup vs baseline: 1.0476x; 1.0476x over previous
#include <cuda_runtime.h>
#include <cuda_bf16.h>
#include <cuda_fp16.h>
#include <cstdint>

// Problem constants (fixed by setup_inputs)
#define B_  4
#define T_  1024
#define C_  1024
#define H_  16
#define DH  64
#define MAXREL 32

// W-scale: keeps relu(..)+1e-6 weights inside fp16 normal range.
#define WSCALE 256.0f
#define WSCALE_INV (1.0f / 256.0f)

// Scratch (allocation-free rule: __device__ globals)
__device__ __half  g_x2 [B_*T_*C_];
__device__ __half  g_w2q[C_*C_], g_w2k[C_*C_], g_w2v[C_*C_], g_w2o[C_*C_];
__device__ __half  g_ath[B_*T_*C_];
__device__ __half  g_Vth[B_*H_*DH*T_];         // V half, [B,H,D,T]
__device__ unsigned g_Qhi[B_*H_*T_*DH/2], g_Qlo[B_*H_*T_*DH/2];  // bf16x2 pairs
__device__ unsigned g_Khi[B_*H_*T_*DH/2], g_Klo[B_*H_*T_*DH/2];

__device__ __forceinline__ uint32_t smem_u32(const void* p) {
    uint32_t a;
    asm("{ .reg .u64 t; cvta.to.shared.u64 t, %1; cvt.u32.u64 %0, t; }"
        : "=r"(a) : "l"(p));
    return a;
}

#define MMA_BF16(acc, a, b0, b1)                                              \
    asm volatile(                                                             \
        "mma.sync.aligned.m16n8k16.row.col.f32.bf16.bf16.f32 "                \
        "{%0,%1,%2,%3}, {%4,%5,%6,%7}, {%8,%9}, {%0,%1,%2,%3};"               \
        : "+f"(acc[0]), "+f"(acc[1]), "+f"(acc[2]), "+f"(acc[3])              \
        : "r"(a[0]), "r"(a[1]), "r"(a[2]), "r"(a[3]), "r"(b0), "r"(b1))

#define MMA_FP16(acc, a, b0, b1)                                              \
    asm volatile(                                                             \
        "mma.sync.aligned.m16n8k16.row.col.f32.f16.f16.f32 "                  \
        "{%0,%1,%2,%3}, {%4,%5,%6,%7}, {%8,%9}, {%0,%1,%2,%3};"               \
        : "+f"(acc[0]), "+f"(acc[1]), "+f"(acc[2]), "+f"(acc[3])              \
        : "r"(a[0]), "r"(a[1]), "r"(a[2]), "r"(a[3]), "r"(b0), "r"(b1))

#define LDSM_X4(r0, r1, r2, r3, addr)                                         \
    asm volatile("ldmatrix.sync.aligned.m8n8.x4.shared.b16 {%0,%1,%2,%3}, [%4];" \
        : "=r"(r0), "=r"(r1), "=r"(r2), "=r"(r3) : "r"(addr))

#define CP_ASYNC16(saddr, gptr)                                               \
    asm volatile("cp.async.cg.shared.global [%0], [%1], 16;"                  \
                 :: "r"(saddr), "l"(gptr) : "memory")
#define CP_COMMIT()      asm volatile("cp.async.commit_group;" ::: "memory")
#define CP_WAIT(n)       asm volatile("cp.async.wait_group %0;" :: "n"(n) : "memory")

// ---------------------------------------------------------------------------
// f32 -> half conversion
// ---------------------------------------------------------------------------
__global__ void cvt_half4(const float* __restrict__ i0, __half* __restrict__ o0,
                          const float* __restrict__ i1, __half* __restrict__ o1,
                          const float* __restrict__ i2, __half* __restrict__ o2,
                          const float* __restrict__ i3, __half* __restrict__ o3,
                          int n)
{
    const float* in  = blockIdx.y == 0 ? i0 : blockIdx.y == 1 ? i1
                     : blockIdx.y == 2 ? i2 : i3;
    __half* out      = blockIdx.y == 0 ? o0 : blockIdx.y == 1 ? o1
                     : blockIdx.y == 2 ? o2 : o3;
    const int i = (blockIdx.x * blockDim.x + threadIdx.x) * 8;
    if (i >= n) return;
    float4 v0 = *(const float4*)(in + i);
    float4 v1 = *(const float4*)(in + i + 4);
    __half2 h[4] = {__floats2half2_rn(v0.x, v0.y), __floats2half2_rn(v0.z, v0.w),
                    __floats2half2_rn(v1.x, v1.y), __floats2half2_rn(v1.z, v1.w)};
    *(uint4*)(out + i) = *(uint4*)h;
}
__global__ void cvt_half(const float* __restrict__ in, __half* __restrict__ out,
                         int n)
{
    const int i = (blockIdx.x * blockDim.x + threadIdx.x) * 8;
    if (i >= n) return;
    float4 v0 = *(const float4*)(in + i);
    float4 v1 = *(const float4*)(in + i + 4);
    __half2 h[4] = {__floats2half2_rn(v0.x, v0.y), __floats2half2_rn(v0.z, v0.w),
                    __floats2half2_rn(v1.x, v1.y), __floats2half2_rn(v1.z, v1.w)};
    *(uint4*)(out + i) = *(uint4*)h;
}

// ---------------------------------------------------------------------------
// fp16 GEMM (round-11 proven config): BK=32, 3-stage cp.async, ldmatrix.
// MODE 0: C row-major [M,N] fp32
// MODE 2: packed bf16 hi/lo pairs out, [B,H,T,DH/2]   (Q, K)
// MODE 3: half out, transposed [B,H,DH,T]             (V)
// ---------------------------------------------------------------------------
#define GST   20
#define STG_U (128 * GST)
#define GEMM_SMEM (3 * 2 * STG_U * 4)   // 61440 B

__device__ __forceinline__ void store_hilo(unsigned* Phi, unsigned* Plo, size_t off,
                                           float x, float y) {
    __nv_bfloat16 hx = __float2bfloat16(x), hy = __float2bfloat16(y);
    __nv_bfloat162 h2(hx, hy);
    __nv_bfloat162 l2(__float2bfloat16(x - __bfloat162float(hx)),
                      __float2bfloat16(y - __bfloat162float(hy)));
    Phi[off] = *(unsigned*)&h2;
    Plo[off] = *(unsigned*)&l2;
}

template<int MODE>
__global__ void __launch_bounds__(256, 2)
gemm_h2(const __half* __restrict__ A, const __half* __restrict__ W,
        const float* __restrict__ bias, float* __restrict__ C,
        unsigned* __restrict__ Phi, unsigned* __restrict__ Plo,
        __half* __restrict__ Vh)
{
    const int K = 1024, N = 1024;
    extern __shared__ unsigned sm[];

    const int t = threadIdx.x;
    const int lane = t & 31, warp = t >> 5;
    const int wm = warp >> 2, wn = warp & 3;
    const int m0 = blockIdx.y * 128, n0 = blockIdx.x * 128;

    const int lrow = lane & 7;
    const int agrp_r = ((lane >> 3) & 1) * 8;
    const int agrp_c = ((lane >> 4) & 1) * 4;
    const int bgrp_r = ((lane >> 4) & 1) * 8;
    const int bgrp_c = ((lane >> 3) & 1) * 4;

    const int r   = t >> 1;
    const int seg = t & 1;
    const __half* Ap = A + (size_t)(m0 + r) * K + seg * 16;
    const __half* Wp = W + (size_t)(n0 + r) * K + seg * 16;
    const uint32_t smbase = smem_u32(sm);
    const uint32_t dstA = smbase + (r * GST + seg * 8) * 4;
    const uint32_t dstB = dstA + STG_U * 4;

    auto issue = [&](int kt) {
        const uint32_t sb = (kt % 3) * (2 * STG_U * 4);
        const __half* a = Ap + kt * 32;
        const __half* b = Wp + kt * 32;
        CP_ASYNC16(dstA + sb,      a);
        CP_ASYNC16(dstA + sb + 16, a + 8);
        CP_ASYNC16(dstB + sb,      b);
        CP_ASYNC16(dstB + sb + 16, b + 8);
        CP_COMMIT();
    };

    float acc[4][4][4];
#pragma unroll
    for (int i = 0; i < 4; i++)
#pragma unroll
        for (int j = 0; j < 4; j++)
#pragma unroll
            for (int x = 0; x < 4; x++) acc[i][j][x] = 0.f;

    issue(0);
    issue(1);

    const int NKT = K / 32;   // 32
    for (int kt = 0; kt < NKT; kt++) {
        CP_WAIT(1);
        __syncthreads();

        const uint32_t sa = smbase + (kt % 3) * 2 * STG_U * 4;
        const uint32_t sb = sa + STG_U * 4;
#pragma unroll
        for (int s = 0; s < 2; s++) {
            const int g0 = s * 8;
            unsigned af[4][4], bf[4][2];
#pragma unroll
            for (int mf = 0; mf < 4; mf++) {
                const int rr = wm * 64 + mf * 16 + agrp_r + lrow;
                LDSM_X4(af[mf][0], af[mf][1], af[mf][2], af[mf][3],
                        sa + (rr * GST + g0 + agrp_c) * 4);
            }
#pragma unroll
            for (int np = 0; np < 2; np++) {
                const int rr = wn * 32 + (np * 2) * 8 + bgrp_r + lrow;
                LDSM_X4(bf[np*2][0], bf[np*2][1], bf[np*2+1][0], bf[np*2+1][1],
                        sb + (rr * GST + g0 + bgrp_c) * 4);
            }
#pragma unroll
            for (int mf = 0; mf < 4; mf++)
#pragma unroll
                for (int nf = 0; nf < 4; nf++)
                    MMA_FP16(acc[mf][nf], af[mf], bf[nf][0], bf[nf][1]);
        }
        if (kt + 2 < NKT) issue(kt + 2);
    }

    // epilogue
#pragma unroll
    for (int nf = 0; nf < 4; nf++) {
        const int col = n0 + wn * 32 + nf * 8 + (lane & 3) * 2;
        const float bv0 = bias[col], bv1 = bias[col + 1];
#pragma unroll
        for (int mf = 0; mf < 4; mf++) {
            const int row = m0 + wm * 64 + mf * 16 + (lane >> 2);
            float2 v0 = make_float2(acc[mf][nf][0] + bv0, acc[mf][nf][1] + bv1);
            float2 v1 = make_float2(acc[mf][nf][2] + bv0, acc[mf][nf][3] + bv1);
            if (MODE == 0) {
                *(float2*)(C + (size_t)row * N + col)       = v0;
                *(float2*)(C + (size_t)(row + 8) * N + col) = v1;
            } else if (MODE == 2) {
                const int h = col >> 6, d = col & 63, pr = d >> 1;
                const int bb = row >> 10, tt = row & 1023;
                const size_t off = ((((size_t)bb * H_ + h) * T_ + tt) * 32) + pr;
                store_hilo(Phi, Plo, off,          v0.x, v0.y);
                store_hilo(Phi, Plo, off + 8 * 32, v1.x, v1.y);
            } else {  // MODE 3: V half, transposed [B,H,D,T]
                const int h = col >> 6, d = col & 63;
                const int bb = row >> 10, tt = row & 1023;
                const size_t vb = (((size_t)bb * H_ + h) * DH + d) * T_ + tt;
                Vh[vb]          = __float2half(v0.x);
                Vh[vb + T_]     = __float2half(v0.y);
                Vh[vb + 8]      = __float2half(v1.x);
                Vh[vb + T_ + 8] = __float2half(v1.y);
            }
        }
    }
}

// ---------------------------------------------------------------------------
// Fused causal algebraic attention v5:
//   - K/V tiles double-buffered, prefetched one full iteration ahead
//   - Q fragments held in registers (loaded once)
//   Stage1: S = Q @ K^T, bf16 hi/lo 3-term k16
//   Stage2: O += (S*W) @ V, fp16 k16
// smem: 9 tiles x 9216B + 512 = 83456 B -> 2 CTA/SM.
// ---------------------------------------------------------------------------
#define PST 36
#define ATILE (64 * PST)          // u32 per tile
#define ATB   (ATILE * 4)         // bytes per tile

__global__ void __launch_bounds__(256, 2)
attn_v5(const unsigned* __restrict__ Qhi, const unsigned* __restrict__ Qlo,
        const unsigned* __restrict__ Khi, const unsigned* __restrict__ Klo,
        const __half* __restrict__ Vtg, const float* __restrict__ rel_bias,
        __half* __restrict__ out)
{
    extern __shared__ unsigned sm[];
    unsigned* Qh_s = sm;                    // tile 0
    unsigned* Ql_s = Qh_s + ATILE;          // tile 1
    unsigned* Kh_s = Ql_s + ATILE;          // tiles 2,3 (buf 0/1)
    unsigned* Kl_s = Kh_s + 2 * ATILE;      // tiles 4,5
    unsigned* Vt_s = Kl_s + 2 * ATILE;      // tiles 6,7
    unsigned* Ws_s = Vt_s + 2 * ATILE;      // tile 8
    float* bh   = (float*)(Ws_s + ATILE);
    float* rsum = bh + 64;

    const int qt = 15 - (int)blockIdx.x;
    const int h  = blockIdx.y;
    const int b  = blockIdx.z;
    const int t  = threadIdx.x;
    const int lane = t & 31, warp = t >> 5;
    const int wm = warp >> 1, wn = warp & 1;
    const int q0 = qt * 64;
    const int bhx = b * H_ + h;

    const int lrow = lane & 7;
    const int agrp_r = ((lane >> 3) & 1) * 8;
    const int agrp_c = ((lane >> 4) & 1) * 4;
    const int bgrp_r = ((lane >> 4) & 1) * 8;
    const int bgrp_c = ((lane >> 3) & 1) * 4;

    const uint32_t qh_b = smem_u32(Qh_s), ql_b = smem_u32(Ql_s);
    const uint32_t kh_b = smem_u32(Kh_s), kl_b = smem_u32(Kl_s);
    const uint32_t vt_b = smem_u32(Vt_s), ws_b = smem_u32(Ws_s);

    const int r4  = t >> 2;
    const int cp8 = (t & 3) * 8;

    const unsigned* Khg = Khi + (size_t)bhx * T_ * 32;
    const unsigned* Klg = Klo + (size_t)bhx * T_ * 32;
    const __half*   Vbg = Vtg + (size_t)bhx * DH * T_;

    // issue K(hi/lo)+V loads for tile kt into buffer buf; ONE commit group
    auto issue = [&](int kt, int buf) {
        const int k0 = kt * 64;
        const size_t koff = (size_t)(k0 + r4) * 32 + cp8;
        const uint32_t kb = kh_b + buf * ATB + (r4 * PST + cp8) * 4;
        const uint32_t lb = kl_b + buf * ATB + (r4 * PST + cp8) * 4;
        CP_ASYNC16(kb,      Khg + koff);
        CP_ASYNC16(kb + 16, Khg + koff + 4);
        CP_ASYNC16(lb,      Klg + koff);
        CP_ASYNC16(lb + 16, Klg + koff + 4);
        const __half* vp = Vbg + (size_t)r4 * T_ + k0 + (t & 3) * 16;
        const uint32_t vb = vt_b + buf * ATB + (r4 * PST + cp8) * 4;
        CP_ASYNC16(vb,      vp);
        CP_ASYNC16(vb + 16, vp + 8);
        CP_COMMIT();
    };

    // prologue: Q loads (group 1), tile 0 (group 2)
    {
        const size_t qoff = ((size_t)bhx * T_ + q0 + r4) * 32 + cp8;
        CP_ASYNC16(qh_b + (r4 * PST + cp8) * 4,      Qhi + qoff);
        CP_ASYNC16(qh_b + (r4 * PST + cp8) * 4 + 16, Qhi + qoff + 4);
        CP_ASYNC16(ql_b + (r4 * PST + cp8) * 4,      Qlo + qoff);
        CP_ASYNC16(ql_b + (r4 * PST + cp8) * 4 + 16, Qlo + qoff + 4);
        CP_COMMIT();
    }
    issue(0, 0);
    if (t < 2 * MAXREL - 1) bh[t] = rel_bias[t * H_ + h];
    if (t < 64) rsum[t] = 0.f;

    // wait for Q (tile-0 group may still be in flight), load Q frags to regs
    CP_WAIT(1);
    __syncthreads();
    unsigned qh[4][4], ql[4][4];
#pragma unroll
    for (int st = 0; st < 4; st++) {
        const int g0 = st * 8;
        const int rr = wm * 16 + agrp_r + lrow;
        LDSM_X4(qh[st][0], qh[st][1], qh[st][2], qh[st][3],
                qh_b + (rr * PST + g0 + agrp_c) * 4);
        LDSM_X4(ql[st][0], ql[st][1], ql[st][2], ql[st][3],
                ql_b + (rr * PST + g0 + agrp_c) * 4);
    }

    float oacc[4][4];
#pragma unroll
    for (int i = 0; i < 4; i++)
#pragma unroll
        for (int j = 0; j < 4; j++) oacc[i][j] = 0.f;
    float rp0 = 0.f, rp1 = 0.f;

    const int ar = wm * 16 + (lane >> 2);

    for (int kt = 0; kt <= qt; kt++) {
        const int buf = kt & 1;
        const int k0 = kt * 64;

        CP_WAIT(0);          // tile kt resident (issued a full iteration ago)
        __syncthreads();     // + all warps done with stage2 on buf^1
        if (kt + 1 <= qt) issue(kt + 1, buf ^ 1);

        // Stage 1: bf16 3-term, Q from registers
        float s[4][4];
#pragma unroll
        for (int i = 0; i < 4; i++)
#pragma unroll
            for (int j = 0; j < 4; j++) s[i][j] = 0.f;

        const uint32_t khb = kh_b + buf * ATB;
        const uint32_t klb = kl_b + buf * ATB;
#pragma unroll
        for (int st = 0; st < 4; st++) {
            const int g0 = st * 8;
            unsigned bhf[4][2], blf[4][2];
#pragma unroll
            for (int np = 0; np < 2; np++) {
                const int rr = wn * 32 + (np * 2) * 8 + bgrp_r + lrow;
                LDSM_X4(bhf[np*2][0], bhf[np*2][1], bhf[np*2+1][0], bhf[np*2+1][1],
                        khb + (rr * PST + g0 + bgrp_c) * 4);
                LDSM_X4(blf[np*2][0], blf[np*2][1], blf[np*2+1][0], blf[np*2+1][1],
                        klb + (rr * PST + g0 + bgrp_c) * 4);
            }
#pragma unroll
            for (int nf = 0; nf < 4; nf++) {
                MMA_BF16(s[nf], qh[st], bhf[nf][0], bhf[nf][1]);
                MMA_BF16(s[nf], qh[st], blf[nf][0], blf[nf][1]);
                MMA_BF16(s[nf], ql[st], bhf[nf][0], bhf[nf][1]);
            }
        }

        // Epilogue -> W (half, scaled) + rsum (unscaled, fp32)
        {
            const int qg0 = q0 + ar;
            const bool diag = (kt == qt);
#pragma unroll
            for (int nf = 0; nf < 4; nf++) {
                const int kg0 = k0 + wn * 32 + nf * 8 + (lane & 3) * 2;
                float w[4];
#pragma unroll
                for (int c = 0; c < 4; c++) {
                    const int qg = qg0 + (c >> 1) * 8;
                    const int kg = kg0 + (c & 1);
                    const int rel = kg - qg;
                    float wv = 0.f;
                    if (!diag || rel <= 0) {
                        const int u = max(rel + (MAXREL - 1), 0);
                        wv = fmaxf(fmaf(s[nf][c], 0.125f, bh[u]), 0.f) + 1e-6f;
                    }
                    w[c] = wv;
                }
                rp0 += w[0] + w[1];
                rp1 += w[2] + w[3];
                const int pc = wn * 16 + nf * 4 + (lane & 3);
                __half2 h0 = __floats2half2_rn(w[0] * WSCALE, w[1] * WSCALE);
                __half2 h1 = __floats2half2_rn(w[2] * WSCALE, w[3] * WSCALE);
                Ws_s[ar * PST + pc]       = *(unsigned*)&h0;
                Ws_s[(ar + 8) * PST + pc] = *(unsigned*)&h1;
            }
        }
        __syncthreads();   // Ws visible to all warps

        // Stage 2: O += W @ V, fp16 k16
        const uint32_t vtb = vt_b + buf * ATB;
#pragma unroll
        for (int st = 0; st < 4; st++) {
            const int g0 = st * 8;
            unsigned a[4], bf[4][2];
            {
                const int rr = wm * 16 + agrp_r + lrow;
                LDSM_X4(a[0], a[1], a[2], a[3],
                        ws_b + (rr * PST + g0 + agrp_c) * 4);
            }
#pragma unroll
            for (int np = 0; np < 2; np++) {
                const int rr = wn * 32 + (np * 2) * 8 + bgrp_r + lrow;
                LDSM_X4(bf[np*2][0], bf[np*2][1], bf[np*2+1][0], bf[np*2+1][1],
                        vtb + (rr * PST + g0 + bgrp_c) * 4);
            }
#pragma unroll
            for (int nf = 0; nf < 4; nf++)
                MMA_FP16(oacc[nf], a, bf[nf][0], bf[nf][1]);
        }
    }

    rp0 += __shfl_xor_sync(0xffffffffu, rp0, 1);
    rp0 += __shfl_xor_sync(0xffffffffu, rp0, 2);
    rp1 += __shfl_xor_sync(0xffffffffu, rp1, 1);
    rp1 += __shfl_xor_sync(0xffffffffu, rp1, 2);
    if ((lane & 3) == 0) {
        atomicAdd(&rsum[ar], rp0);
        atomicAdd(&rsum[ar + 8], rp1);
    }
    __syncthreads();

    const float inv0 = WSCALE_INV / (rsum[ar] + 1e-6f);
    const float inv1 = WSCALE_INV / (rsum[ar + 8] + 1e-6f);
#pragma unroll
    for (int nf = 0; nf < 4; nf++) {
        const int d = wn * 32 + nf * 8 + (lane & 3) * 2;
        __half* dst0 = out + (size_t)(b * T_ + q0 + ar) * C_ + h * DH + d;
        __half* dst1 = out + (size_t)(b * T_ + q0 + ar + 8) * C_ + h * DH + d;
        __half2 h0 = __floats2half2_rn(oacc[nf][0] * inv0, oacc[nf][1] * inv0);
        __half2 h1 = __floats2half2_rn(oacc[nf][2] * inv1, oacc[nf][3] * inv1);
        *(__half2*)dst0 = h0;
        *(__half2*)dst1 = h1;
    }
}

#define ATTN_SMEM ((9 * ATILE + 128) * 4)   // 83456 B

// ---------------------------------------------------------------------------
extern "C" void kernel_launch(void* const* d_in, const int* in_sizes, int n_in,
                              void* d_out, int out_size)
{
    const float* x   = (const float*)d_in[0];
    const float* Wq  = (const float*)d_in[2];
    const float* bq  = (const float*)d_in[3];
    const float* Wk  = (const float*)d_in[4];
    const float* bk  = (const float*)d_in[5];
    const float* Wv  = (const float*)d_in[6];
    const float* bv  = (const float*)d_in[7];
    const float* Wo  = (const float*)d_in[8];
    const float* bo  = (const float*)d_in[9];
    const float* rel = (const float*)d_in[10];

    __half *x2, *w2q, *w2k, *w2v, *w2o, *ath, *vth;
    unsigned *qhi, *qlo, *khi, *klo;
    cudaGetSymbolAddress((void**)&x2,  g_x2);
    cudaGetSymbolAddress((void**)&w2q, g_w2q);
    cudaGetSymbolAddress((void**)&w2k, g_w2k);
    cudaGetSymbolAddress((void**)&w2v, g_w2v);
    cudaGetSymbolAddress((void**)&w2o, g_w2o);
    cudaGetSymbolAddress((void**)&ath, g_ath);
    cudaGetSymbolAddress((void**)&vth, g_Vth);
    cudaGetSymbolAddress((void**)&qhi, g_Qhi);
    cudaGetSymbolAddress((void**)&qlo, g_Qlo);
    cudaGetSymbolAddress((void**)&khi, g_Khi);
    cudaGetSymbolAddress((void**)&klo, g_Klo);

    static int configured = 0;
    if (!configured) {
        cudaFuncSetAttribute(attn_v5, cudaFuncAttributeMaxDynamicSharedMemorySize,
                             ATTN_SMEM);
        cudaFuncSetAttribute(gemm_h2<0>, cudaFuncAttributeMaxDynamicSharedMemorySize,
                             GEMM_SMEM);
        cudaFuncSetAttribute(gemm_h2<2>, cudaFuncAttributeMaxDynamicSharedMemorySize,
                             GEMM_SMEM);
        cudaFuncSetAttribute(gemm_h2<3>, cudaFuncAttributeMaxDynamicSharedMemorySize,
                             GEMM_SMEM);
        configured = 1;
    }

    const int NX = B_ * T_ * C_, NW = C_ * C_;
    cvt_half4<<<dim3(NW / 2048, 4), 256>>>(Wq, w2q, Wk, w2k, Wv, w2v, Wo, w2o, NW);
    cvt_half<<<NX / 2048, 256>>>(x, x2, NX);

    dim3 gg(C_ / 128, (B_ * T_) / 128);  // (8, 32)
    gemm_h2<2><<<gg, 256, GEMM_SMEM>>>(x2, w2q, bq, nullptr, qhi, qlo, nullptr);
    gemm_h2<2><<<gg, 256, GEMM_SMEM>>>(x2, w2k, bk, nullptr, khi, klo, nullptr);
    gemm_h2<3><<<gg, 256, GEMM_SMEM>>>(x2, w2v, bv, nullptr, nullptr, nullptr, vth);

    attn_v5<<<dim3(16, H_, B_), 256, ATTN_SMEM>>>(qhi, qlo, khi, klo, vth, rel, ath);

    gemm_h2<0><<<gg, 256, GEMM_SMEM>>>(ath, w2o, bo, (float*)d_out, nullptr, nullptr, nullptr);
}

// round 14
// speedup vs baseline: 1.1105x; 1.0601x over previous
#include <cuda_runtime.h>
#include <cuda_bf16.h>
#include <cuda_fp16.h>
#include <cstdint>

// Problem constants (fixed by setup_inputs)
#define B_  4
#define T_  1024
#define C_  1024
#define H_  16
#define DH  64
#define MAXREL 32

// W-scale: keeps relu(..)+1e-6 weights inside fp16 normal range.
#define WSCALE 256.0f
#define WSCALE_INV (1.0f / 256.0f)

// Scratch (allocation-free rule: __device__ globals)
__device__ __half  g_x2 [B_*T_*C_];
__device__ __half  g_w2q[C_*C_], g_w2k[C_*C_], g_w2v[C_*C_], g_w2o[C_*C_];
__device__ __half  g_ath[B_*T_*C_];
__device__ __half  g_Vth[B_*H_*DH*T_];         // V half, [B,H,D,T]
__device__ unsigned g_Qhi[B_*H_*T_*DH/2], g_Qlo[B_*H_*T_*DH/2];  // bf16x2 pairs
__device__ unsigned g_Khi[B_*H_*T_*DH/2], g_Klo[B_*H_*T_*DH/2];

__device__ __forceinline__ uint32_t smem_u32(const void* p) {
    uint32_t a;
    asm("{ .reg .u64 t; cvta.to.shared.u64 t, %1; cvt.u32.u64 %0, t; }"
        : "=r"(a) : "l"(p));
    return a;
}

#define MMA_BF16(acc, a, b0, b1)                                              \
    asm volatile(                                                             \
        "mma.sync.aligned.m16n8k16.row.col.f32.bf16.bf16.f32 "                \
        "{%0,%1,%2,%3}, {%4,%5,%6,%7}, {%8,%9}, {%0,%1,%2,%3};"               \
        : "+f"(acc[0]), "+f"(acc[1]), "+f"(acc[2]), "+f"(acc[3])              \
        : "r"(a[0]), "r"(a[1]), "r"(a[2]), "r"(a[3]), "r"(b0), "r"(b1))

#define MMA_FP16(acc, a, b0, b1)                                              \
    asm volatile(                                                             \
        "mma.sync.aligned.m16n8k16.row.col.f32.f16.f16.f32 "                  \
        "{%0,%1,%2,%3}, {%4,%5,%6,%7}, {%8,%9}, {%0,%1,%2,%3};"               \
        : "+f"(acc[0]), "+f"(acc[1]), "+f"(acc[2]), "+f"(acc[3])              \
        : "r"(a[0]), "r"(a[1]), "r"(a[2]), "r"(a[3]), "r"(b0), "r"(b1))

#define LDSM_X4(r0, r1, r2, r3, addr)                                         \
    asm volatile("ldmatrix.sync.aligned.m8n8.x4.shared.b16 {%0,%1,%2,%3}, [%4];" \
        : "=r"(r0), "=r"(r1), "=r"(r2), "=r"(r3) : "r"(addr))

#define CP_ASYNC16(saddr, gptr)                                               \
    asm volatile("cp.async.cg.shared.global [%0], [%1], 16;"                  \
                 :: "r"(saddr), "l"(gptr) : "memory")
#define CP_COMMIT()      asm volatile("cp.async.commit_group;" ::: "memory")
#define CP_WAIT(n)       asm volatile("cp.async.wait_group %0;" :: "n"(n) : "memory")

// ---------------------------------------------------------------------------
// f32 -> half conversion, single launch: by 0..3 = weights (n=NW), by 4 = x
// ---------------------------------------------------------------------------
__global__ void cvt_all(const float* __restrict__ i0, __half* __restrict__ o0,
                        const float* __restrict__ i1, __half* __restrict__ o1,
                        const float* __restrict__ i2, __half* __restrict__ o2,
                        const float* __restrict__ i3, __half* __restrict__ o3,
                        const float* __restrict__ i4, __half* __restrict__ o4,
                        int nw, int nx)
{
    const int by = blockIdx.y;
    const float* in  = by == 0 ? i0 : by == 1 ? i1 : by == 2 ? i2
                     : by == 3 ? i3 : i4;
    __half* out      = by == 0 ? o0 : by == 1 ? o1 : by == 2 ? o2
                     : by == 3 ? o3 : o4;
    const int n = (by < 4) ? nw : nx;
    const int i = (blockIdx.x * blockDim.x + threadIdx.x) * 8;
    if (i >= n) return;
    float4 v0 = *(const float4*)(in + i);
    float4 v1 = *(const float4*)(in + i + 4);
    __half2 h[4] = {__floats2half2_rn(v0.x, v0.y), __floats2half2_rn(v0.z, v0.w),
                    __floats2half2_rn(v1.x, v1.y), __floats2half2_rn(v1.z, v1.w)};
    *(uint4*)(out + i) = *(uint4*)h;
}

// ---------------------------------------------------------------------------
// fp16 GEMM (round-11 proven inner loop): BK=32, 3-stage cp.async, ldmatrix.
// FUSED=1: Q/K/V in ONE launch, grid (24,32); which = bx>>3.
//          which 0/1 -> packed bf16 hi/lo pairs [B,H,T,DH/2] (Q, K)
//          which 2   -> half, transposed [B,H,DH,T]          (V)
// FUSED=0: output GEMM, grid (8,32), fp32 C row-major.
// ---------------------------------------------------------------------------
#define GST   20
#define STG_U (128 * GST)
#define GEMM_SMEM (3 * 2 * STG_U * 4)   // 61440 B

__device__ __forceinline__ void store_hilo(unsigned* Phi, unsigned* Plo, size_t off,
                                           float x, float y) {
    __nv_bfloat16 hx = __float2bfloat16(x), hy = __float2bfloat16(y);
    __nv_bfloat162 h2(hx, hy);
    __nv_bfloat162 l2(__float2bfloat16(x - __bfloat162float(hx)),
                      __float2bfloat16(y - __bfloat162float(hy)));
    Phi[off] = *(unsigned*)&h2;
    Plo[off] = *(unsigned*)&l2;
}

template<int FUSED>
__global__ void __launch_bounds__(256, 2)
gemm_h2(const __half* __restrict__ A,
        const __half* __restrict__ W0, const __half* __restrict__ W1,
        const __half* __restrict__ W2,
        const float* __restrict__ b0, const float* __restrict__ b1,
        const float* __restrict__ b2,
        float* __restrict__ C,
        unsigned* __restrict__ qhi, unsigned* __restrict__ qlo,
        unsigned* __restrict__ khi, unsigned* __restrict__ klo,
        __half* __restrict__ Vh)
{
    const int K = 1024, N = 1024;
    extern __shared__ unsigned sm[];

    const int which = FUSED ? ((int)blockIdx.x >> 3) : 0;
    const __half* W = FUSED ? (which == 0 ? W0 : which == 1 ? W1 : W2) : W0;
    const float* bias = FUSED ? (which == 0 ? b0 : which == 1 ? b1 : b2) : b0;

    const int t = threadIdx.x;
    const int lane = t & 31, warp = t >> 5;
    const int wm = warp >> 2, wn = warp & 3;
    const int m0 = blockIdx.y * 128, n0 = ((int)blockIdx.x & 7) * 128;

    const int lrow = lane & 7;
    const int agrp_r = ((lane >> 3) & 1) * 8;
    const int agrp_c = ((lane >> 4) & 1) * 4;
    const int bgrp_r = ((lane >> 4) & 1) * 8;
    const int bgrp_c = ((lane >> 3) & 1) * 4;

    const int r   = t >> 1;
    const int seg = t & 1;
    const __half* Ap = A + (size_t)(m0 + r) * K + seg * 16;
    const __half* Wp = W + (size_t)(n0 + r) * K + seg * 16;
    const uint32_t smbase = smem_u32(sm);
    const uint32_t dstA = smbase + (r * GST + seg * 8) * 4;
    const uint32_t dstB = dstA + STG_U * 4;

    auto issue = [&](int kt) {
        const uint32_t sb = (kt % 3) * (2 * STG_U * 4);
        const __half* a = Ap + kt * 32;
        const __half* b = Wp + kt * 32;
        CP_ASYNC16(dstA + sb,      a);
        CP_ASYNC16(dstA + sb + 16, a + 8);
        CP_ASYNC16(dstB + sb,      b);
        CP_ASYNC16(dstB + sb + 16, b + 8);
        CP_COMMIT();
    };

    float acc[4][4][4];
#pragma unroll
    for (int i = 0; i < 4; i++)
#pragma unroll
        for (int j = 0; j < 4; j++)
#pragma unroll
            for (int x = 0; x < 4; x++) acc[i][j][x] = 0.f;

    issue(0);
    issue(1);

    const int NKT = K / 32;   // 32
    for (int kt = 0; kt < NKT; kt++) {
        CP_WAIT(1);
        __syncthreads();

        const uint32_t sa = smbase + (kt % 3) * 2 * STG_U * 4;
        const uint32_t sb = sa + STG_U * 4;
#pragma unroll
        for (int s = 0; s < 2; s++) {
            const int g0 = s * 8;
            unsigned af[4][4], bf[4][2];
#pragma unroll
            for (int mf = 0; mf < 4; mf++) {
                const int rr = wm * 64 + mf * 16 + agrp_r + lrow;
                LDSM_X4(af[mf][0], af[mf][1], af[mf][2], af[mf][3],
                        sa + (rr * GST + g0 + agrp_c) * 4);
            }
#pragma unroll
            for (int np = 0; np < 2; np++) {
                const int rr = wn * 32 + (np * 2) * 8 + bgrp_r + lrow;
                LDSM_X4(bf[np*2][0], bf[np*2][1], bf[np*2+1][0], bf[np*2+1][1],
                        sb + (rr * GST + g0 + bgrp_c) * 4);
            }
#pragma unroll
            for (int mf = 0; mf < 4; mf++)
#pragma unroll
                for (int nf = 0; nf < 4; nf++)
                    MMA_FP16(acc[mf][nf], af[mf], bf[nf][0], bf[nf][1]);
        }
        if (kt + 2 < NKT) issue(kt + 2);
    }

    // epilogue
#pragma unroll
    for (int nf = 0; nf < 4; nf++) {
        const int col = n0 + wn * 32 + nf * 8 + (lane & 3) * 2;
        const float bv0 = bias[col], bv1 = bias[col + 1];
#pragma unroll
        for (int mf = 0; mf < 4; mf++) {
            const int row = m0 + wm * 64 + mf * 16 + (lane >> 2);
            float2 v0 = make_float2(acc[mf][nf][0] + bv0, acc[mf][nf][1] + bv1);
            float2 v1 = make_float2(acc[mf][nf][2] + bv0, acc[mf][nf][3] + bv1);
            if (!FUSED) {
                *(float2*)(C + (size_t)row * N + col)       = v0;
                *(float2*)(C + (size_t)(row + 8) * N + col) = v1;
            } else if (which < 2) {
                unsigned* Phi = which == 0 ? qhi : khi;
                unsigned* Plo = which == 0 ? qlo : klo;
                const int h = col >> 6, d = col & 63, pr = d >> 1;
                const int bb = row >> 10, tt = row & 1023;
                const size_t off = ((((size_t)bb * H_ + h) * T_ + tt) * 32) + pr;
                store_hilo(Phi, Plo, off,          v0.x, v0.y);
                store_hilo(Phi, Plo, off + 8 * 32, v1.x, v1.y);
            } else {  // V half, transposed [B,H,D,T]
                const int h = col >> 6, d = col & 63;
                const int bb = row >> 10, tt = row & 1023;
                const size_t vb = (((size_t)bb * H_ + h) * DH + d) * T_ + tt;
                Vh[vb]          = __float2half(v0.x);
                Vh[vb + T_]     = __float2half(v0.y);
                Vh[vb + 8]      = __float2half(v1.x);
                Vh[vb + T_ + 8] = __float2half(v1.y);
            }
        }
    }
}

// ---------------------------------------------------------------------------
// Fused causal algebraic attention v5 (unchanged from round 13):
//   K/V double-buffered + prefetched one iteration ahead; Q frags in regs.
// ---------------------------------------------------------------------------
#define PST 36
#define ATILE (64 * PST)
#define ATB   (ATILE * 4)

__global__ void __launch_bounds__(256, 2)
attn_v5(const unsigned* __restrict__ Qhi, const unsigned* __restrict__ Qlo,
        const unsigned* __restrict__ Khi, const unsigned* __restrict__ Klo,
        const __half* __restrict__ Vtg, const float* __restrict__ rel_bias,
        __half* __restrict__ out)
{
    extern __shared__ unsigned sm[];
    unsigned* Qh_s = sm;
    unsigned* Ql_s = Qh_s + ATILE;
    unsigned* Kh_s = Ql_s + ATILE;
    unsigned* Kl_s = Kh_s + 2 * ATILE;
    unsigned* Vt_s = Kl_s + 2 * ATILE;
    unsigned* Ws_s = Vt_s + 2 * ATILE;
    float* bh   = (float*)(Ws_s + ATILE);
    float* rsum = bh + 64;

    const int qt = 15 - (int)blockIdx.x;
    const int h  = blockIdx.y;
    const int b  = blockIdx.z;
    const int t  = threadIdx.x;
    const int lane = t & 31, warp = t >> 5;
    const int wm = warp >> 1, wn = warp & 1;
    const int q0 = qt * 64;
    const int bhx = b * H_ + h;

    const int lrow = lane & 7;
    const int agrp_r = ((lane >> 3) & 1) * 8;
    const int agrp_c = ((lane >> 4) & 1) * 4;
    const int bgrp_r = ((lane >> 4) & 1) * 8;
    const int bgrp_c = ((lane >> 3) & 1) * 4;

    const uint32_t qh_b = smem_u32(Qh_s), ql_b = smem_u32(Ql_s);
    const uint32_t kh_b = smem_u32(Kh_s), kl_b = smem_u32(Kl_s);
    const uint32_t vt_b = smem_u32(Vt_s), ws_b = smem_u32(Ws_s);

    const int r4  = t >> 2;
    const int cp8 = (t & 3) * 8;

    const unsigned* Khg = Khi + (size_t)bhx * T_ * 32;
    const unsigned* Klg = Klo + (size_t)bhx * T_ * 32;
    const __half*   Vbg = Vtg + (size_t)bhx * DH * T_;

    auto issue = [&](int kt, int buf) {
        const int k0 = kt * 64;
        const size_t koff = (size_t)(k0 + r4) * 32 + cp8;
        const uint32_t kb = kh_b + buf * ATB + (r4 * PST + cp8) * 4;
        const uint32_t lb = kl_b + buf * ATB + (r4 * PST + cp8) * 4;
        CP_ASYNC16(kb,      Khg + koff);
        CP_ASYNC16(kb + 16, Khg + koff + 4);
        CP_ASYNC16(lb,      Klg + koff);
        CP_ASYNC16(lb + 16, Klg + koff + 4);
        const __half* vp = Vbg + (size_t)r4 * T_ + k0 + (t & 3) * 16;
        const uint32_t vb = vt_b + buf * ATB + (r4 * PST + cp8) * 4;
        CP_ASYNC16(vb,      vp);
        CP_ASYNC16(vb + 16, vp + 8);
        CP_COMMIT();
    };

    {
        const size_t qoff = ((size_t)bhx * T_ + q0 + r4) * 32 + cp8;
        CP_ASYNC16(qh_b + (r4 * PST + cp8) * 4,      Qhi + qoff);
        CP_ASYNC16(qh_b + (r4 * PST + cp8) * 4 + 16, Qhi + qoff + 4);
        CP_ASYNC16(ql_b + (r4 * PST + cp8) * 4,      Qlo + qoff);
        CP_ASYNC16(ql_b + (r4 * PST + cp8) * 4 + 16, Qlo + qoff + 4);
        CP_COMMIT();
    }
    issue(0, 0);
    if (t < 2 * MAXREL - 1) bh[t] = rel_bias[t * H_ + h];
    if (t < 64) rsum[t] = 0.f;

    CP_WAIT(1);
    __syncthreads();
    unsigned qh[4][4], ql[4][4];
#pragma unroll
    for (int st = 0; st < 4; st++) {
        const int g0 = st * 8;
        const int rr = wm * 16 + agrp_r + lrow;
        LDSM_X4(qh[st][0], qh[st][1], qh[st][2], qh[st][3],
                qh_b + (rr * PST + g0 + agrp_c) * 4);
        LDSM_X4(ql[st][0], ql[st][1], ql[st][2], ql[st][3],
                ql_b + (rr * PST + g0 + agrp_c) * 4);
    }

    float oacc[4][4];
#pragma unroll
    for (int i = 0; i < 4; i++)
#pragma unroll
        for (int j = 0; j < 4; j++) oacc[i][j] = 0.f;
    float rp0 = 0.f, rp1 = 0.f;

    const int ar = wm * 16 + (lane >> 2);

    for (int kt = 0; kt <= qt; kt++) {
        const int buf = kt & 1;
        const int k0 = kt * 64;

        CP_WAIT(0);
        __syncthreads();
        if (kt + 1 <= qt) issue(kt + 1, buf ^ 1);

        float s[4][4];
#pragma unroll
        for (int i = 0; i < 4; i++)
#pragma unroll
            for (int j = 0; j < 4; j++) s[i][j] = 0.f;

        const uint32_t khb = kh_b + buf * ATB;
        const uint32_t klb = kl_b + buf * ATB;
#pragma unroll
        for (int st = 0; st < 4; st++) {
            const int g0 = st * 8;
            unsigned bhf[4][2], blf[4][2];
#pragma unroll
            for (int np = 0; np < 2; np++) {
                const int rr = wn * 32 + (np * 2) * 8 + bgrp_r + lrow;
                LDSM_X4(bhf[np*2][0], bhf[np*2][1], bhf[np*2+1][0], bhf[np*2+1][1],
                        khb + (rr * PST + g0 + bgrp_c) * 4);
                LDSM_X4(blf[np*2][0], blf[np*2][1], blf[np*2+1][0], blf[np*2+1][1],
                        klb + (rr * PST + g0 + bgrp_c) * 4);
            }
#pragma unroll
            for (int nf = 0; nf < 4; nf++) {
                MMA_BF16(s[nf], qh[st], bhf[nf][0], bhf[nf][1]);
                MMA_BF16(s[nf], qh[st], blf[nf][0], blf[nf][1]);
                MMA_BF16(s[nf], ql[st], bhf[nf][0], bhf[nf][1]);
            }
        }

        {
            const int qg0 = q0 + ar;
            const bool diag = (kt == qt);
#pragma unroll
            for (int nf = 0; nf < 4; nf++) {
                const int kg0 = k0 + wn * 32 + nf * 8 + (lane & 3) * 2;
                float w[4];
#pragma unroll
                for (int c = 0; c < 4; c++) {
                    const int qg = qg0 + (c >> 1) * 8;
                    const int kg = kg0 + (c & 1);
                    const int rel = kg - qg;
                    float wv = 0.f;
                    if (!diag || rel <= 0) {
                        const int u = max(rel + (MAXREL - 1), 0);
                        wv = fmaxf(fmaf(s[nf][c], 0.125f, bh[u]), 0.f) + 1e-6f;
                    }
                    w[c] = wv;
                }
                rp0 += w[0] + w[1];
                rp1 += w[2] + w[3];
                const int pc = wn * 16 + nf * 4 + (lane & 3);
                __half2 h0 = __floats2half2_rn(w[0] * WSCALE, w[1] * WSCALE);
                __half2 h1 = __floats2half2_rn(w[2] * WSCALE, w[3] * WSCALE);
                Ws_s[ar * PST + pc]       = *(unsigned*)&h0;
                Ws_s[(ar + 8) * PST + pc] = *(unsigned*)&h1;
            }
        }
        __syncthreads();

        const uint32_t vtb = vt_b + buf * ATB;
#pragma unroll
        for (int st = 0; st < 4; st++) {
            const int g0 = st * 8;
            unsigned a[4], bf[4][2];
            {
                const int rr = wm * 16 + agrp_r + lrow;
                LDSM_X4(a[0], a[1], a[2], a[3],
                        ws_b + (rr * PST + g0 + agrp_c) * 4);
            }
#pragma unroll
            for (int np = 0; np < 2; np++) {
                const int rr = wn * 32 + (np * 2) * 8 + bgrp_r + lrow;
                LDSM_X4(bf[np*2][0], bf[np*2][1], bf[np*2+1][0], bf[np*2+1][1],
                        vtb + (rr * PST + g0 + bgrp_c) * 4);
            }
#pragma unroll
            for (int nf = 0; nf < 4; nf++)
                MMA_FP16(oacc[nf], a, bf[nf][0], bf[nf][1]);
        }
    }

    rp0 += __shfl_xor_sync(0xffffffffu, rp0, 1);
    rp0 += __shfl_xor_sync(0xffffffffu, rp0, 2);
    rp1 += __shfl_xor_sync(0xffffffffu, rp1, 1);
    rp1 += __shfl_xor_sync(0xffffffffu, rp1, 2);
    if ((lane & 3) == 0) {
        atomicAdd(&rsum[ar], rp0);
        atomicAdd(&rsum[ar + 8], rp1);
    }
    __syncthreads();

    const float inv0 = WSCALE_INV / (rsum[ar] + 1e-6f);
    const float inv1 = WSCALE_INV / (rsum[ar + 8] + 1e-6f);
#pragma unroll
    for (int nf = 0; nf < 4; nf++) {
        const int d = wn * 32 + nf * 8 + (lane & 3) * 2;
        __half* dst0 = out + (size_t)(b * T_ + q0 + ar) * C_ + h * DH + d;
        __half* dst1 = out + (size_t)(b * T_ + q0 + ar + 8) * C_ + h * DH + d;
        __half2 h0 = __floats2half2_rn(oacc[nf][0] * inv0, oacc[nf][1] * inv0);
        __half2 h1 = __floats2half2_rn(oacc[nf][2] * inv1, oacc[nf][3] * inv1);
        *(__half2*)dst0 = h0;
        *(__half2*)dst1 = h1;
    }
}

#define ATTN_SMEM ((9 * ATILE + 128) * 4)   // 83456 B

// ---------------------------------------------------------------------------
extern "C" void kernel_launch(void* const* d_in, const int* in_sizes, int n_in,
                              void* d_out, int out_size)
{
    const float* x   = (const float*)d_in[0];
    const float* Wq  = (const float*)d_in[2];
    const float* bq  = (const float*)d_in[3];
    const float* Wk  = (const float*)d_in[4];
    const float* bk  = (const float*)d_in[5];
    const float* Wv  = (const float*)d_in[6];
    const float* bv  = (const float*)d_in[7];
    const float* Wo  = (const float*)d_in[8];
    const float* bo  = (const float*)d_in[9];
    const float* rel = (const float*)d_in[10];

    __half *x2, *w2q, *w2k, *w2v, *w2o, *ath, *vth;
    unsigned *qhi, *qlo, *khi, *klo;
    cudaGetSymbolAddress((void**)&x2,  g_x2);
    cudaGetSymbolAddress((void**)&w2q, g_w2q);
    cudaGetSymbolAddress((void**)&w2k, g_w2k);
    cudaGetSymbolAddress((void**)&w2v, g_w2v);
    cudaGetSymbolAddress((void**)&w2o, g_w2o);
    cudaGetSymbolAddress((void**)&ath, g_ath);
    cudaGetSymbolAddress((void**)&vth, g_Vth);
    cudaGetSymbolAddress((void**)&qhi, g_Qhi);
    cudaGetSymbolAddress((void**)&qlo, g_Qlo);
    cudaGetSymbolAddress((void**)&khi, g_Khi);
    cudaGetSymbolAddress((void**)&klo, g_Klo);

    static int configured = 0;
    if (!configured) {
        cudaFuncSetAttribute(attn_v5, cudaFuncAttributeMaxDynamicSharedMemorySize,
                             ATTN_SMEM);
        cudaFuncSetAttribute(gemm_h2<0>, cudaFuncAttributeMaxDynamicSharedMemorySize,
                             GEMM_SMEM);
        cudaFuncSetAttribute(gemm_h2<1>, cudaFuncAttributeMaxDynamicSharedMemorySize,
                             GEMM_SMEM);
        configured = 1;
    }

    const int NX = B_ * T_ * C_, NW = C_ * C_;
    // one conversion launch: 4 weight matrices + x (grid.x sized for x)
    cvt_all<<<dim3(NX / 2048, 5), 256>>>(Wq, w2q, Wk, w2k, Wv, w2v, Wo, w2o,
                                         x, x2, NW, NX);

    // Fused Q/K/V projections: ONE launch, 768 CTAs (grid 24 x 32)
    gemm_h2<1><<<dim3(24, 32), 256, GEMM_SMEM>>>(
        x2, w2q, w2k, w2v, bq, bk, bv, nullptr, qhi, qlo, khi, klo, vth);

    attn_v5<<<dim3(16, H_, B_), 256, ATTN_SMEM>>>(qhi, qlo, khi, klo, vth, rel, ath);

    gemm_h2<0><<<dim3(8, 32), 256, GEMM_SMEM>>>(
        ath, w2o, nullptr, nullptr, bo, nullptr, nullptr,
        (float*)d_out, nullptr, nullptr, nullptr, nullptr, nullptr);
}

// round 15
// speedup vs baseline: 1.2626x; 1.1369x over previous
#include <cuda_runtime.h>
#include <cuda_bf16.h>
#include <cuda_fp16.h>
#include <cstdint>

// Problem constants (fixed by setup_inputs)
#define B_  4
#define T_  1024
#define C_  1024
#define H_  16
#define DH  64
#define MAXREL 32

// W-scale: keeps relu(..)+1e-6 weights inside fp16 normal range.
#define WSCALE 256.0f
#define WSCALE_INV (1.0f / 256.0f)

// Scratch (allocation-free rule: __device__ globals)
__device__ __half  g_x2 [B_*T_*C_];
__device__ __half  g_w2q[C_*C_], g_w2k[C_*C_], g_w2v[C_*C_], g_w2o[C_*C_];
__device__ __half  g_ath[B_*T_*C_];
__device__ __half  g_Qh [B_*H_*T_*DH];         // Q half, [B,H,T,DH]
__device__ __half  g_Kh [B_*H_*T_*DH];         // K half, [B,H,T,DH]
__device__ __half  g_Vth[B_*H_*DH*T_];         // V half, [B,H,D,T]

__device__ __forceinline__ uint32_t smem_u32(const void* p) {
    uint32_t a;
    asm("{ .reg .u64 t; cvta.to.shared.u64 t, %1; cvt.u32.u64 %0, t; }"
        : "=r"(a) : "l"(p));
    return a;
}

#define MMA_FP16(acc, a, b0, b1)                                              \
    asm volatile(                                                             \
        "mma.sync.aligned.m16n8k16.row.col.f32.f16.f16.f32 "                  \
        "{%0,%1,%2,%3}, {%4,%5,%6,%7}, {%8,%9}, {%0,%1,%2,%3};"               \
        : "+f"(acc[0]), "+f"(acc[1]), "+f"(acc[2]), "+f"(acc[3])              \
        : "r"(a[0]), "r"(a[1]), "r"(a[2]), "r"(a[3]), "r"(b0), "r"(b1))

#define LDSM_X4(r0, r1, r2, r3, addr)                                         \
    asm volatile("ldmatrix.sync.aligned.m8n8.x4.shared.b16 {%0,%1,%2,%3}, [%4];" \
        : "=r"(r0), "=r"(r1), "=r"(r2), "=r"(r3) : "r"(addr))

#define CP_ASYNC16(saddr, gptr)                                               \
    asm volatile("cp.async.cg.shared.global [%0], [%1], 16;"                  \
                 :: "r"(saddr), "l"(gptr) : "memory")
#define CP_COMMIT()      asm volatile("cp.async.commit_group;" ::: "memory")
#define CP_WAIT(n)       asm volatile("cp.async.wait_group %0;" :: "n"(n) : "memory")

// ---------------------------------------------------------------------------
// f32 -> half conversion, single launch: by 0..3 = weights (n=NW), by 4 = x
// ---------------------------------------------------------------------------
__global__ void cvt_all(const float* __restrict__ i0, __half* __restrict__ o0,
                        const float* __restrict__ i1, __half* __restrict__ o1,
                        const float* __restrict__ i2, __half* __restrict__ o2,
                        const float* __restrict__ i3, __half* __restrict__ o3,
                        const float* __restrict__ i4, __half* __restrict__ o4,
                        int nw, int nx)
{
    const int by = blockIdx.y;
    const float* in  = by == 0 ? i0 : by == 1 ? i1 : by == 2 ? i2
                     : by == 3 ? i3 : i4;
    __half* out      = by == 0 ? o0 : by == 1 ? o1 : by == 2 ? o2
                     : by == 3 ? o3 : o4;
    const int n = (by < 4) ? nw : nx;
    const int i = (blockIdx.x * blockDim.x + threadIdx.x) * 8;
    if (i >= n) return;
    float4 v0 = *(const float4*)(in + i);
    float4 v1 = *(const float4*)(in + i + 4);
    __half2 h[4] = {__floats2half2_rn(v0.x, v0.y), __floats2half2_rn(v0.z, v0.w),
                    __floats2half2_rn(v1.x, v1.y), __floats2half2_rn(v1.z, v1.w)};
    *(uint4*)(out + i) = *(uint4*)h;
}

// ---------------------------------------------------------------------------
// fp16 GEMM: BK=32, 3-stage cp.async, ldmatrix.
// FUSED=1: Q/K/V in ONE launch, grid (24,32); which = bx>>3.
//          which 0/1 -> half [B,H,T,DH]        (Q, K)
//          which 2   -> half, transposed [B,H,DH,T]  (V)
// FUSED=0: output GEMM, grid (8,32), fp32 C row-major.
// ---------------------------------------------------------------------------
#define GST   20
#define STG_U (128 * GST)
#define GEMM_SMEM (3 * 2 * STG_U * 4)   // 61440 B

template<int FUSED>
__global__ void __launch_bounds__(256, 2)
gemm_h2(const __half* __restrict__ A,
        const __half* __restrict__ W0, const __half* __restrict__ W1,
        const __half* __restrict__ W2,
        const float* __restrict__ b0, const float* __restrict__ b1,
        const float* __restrict__ b2,
        float* __restrict__ C,
        __half* __restrict__ Qf, __half* __restrict__ Kf,
        __half* __restrict__ Vh)
{
    const int K = 1024, N = 1024;
    extern __shared__ unsigned sm[];

    const int which = FUSED ? ((int)blockIdx.x >> 3) : 0;
    const __half* W = FUSED ? (which == 0 ? W0 : which == 1 ? W1 : W2) : W0;
    const float* bias = FUSED ? (which == 0 ? b0 : which == 1 ? b1 : b2) : b0;

    const int t = threadIdx.x;
    const int lane = t & 31, warp = t >> 5;
    const int wm = warp >> 2, wn = warp & 3;
    const int m0 = blockIdx.y * 128, n0 = ((int)blockIdx.x & 7) * 128;

    const int lrow = lane & 7;
    const int agrp_r = ((lane >> 3) & 1) * 8;
    const int agrp_c = ((lane >> 4) & 1) * 4;
    const int bgrp_r = ((lane >> 4) & 1) * 8;
    const int bgrp_c = ((lane >> 3) & 1) * 4;

    const int r   = t >> 1;
    const int seg = t & 1;
    const __half* Ap = A + (size_t)(m0 + r) * K + seg * 16;
    const __half* Wp = W + (size_t)(n0 + r) * K + seg * 16;
    const uint32_t smbase = smem_u32(sm);
    const uint32_t dstA = smbase + (r * GST + seg * 8) * 4;
    const uint32_t dstB = dstA + STG_U * 4;

    auto issue = [&](int kt) {
        const uint32_t sb = (kt % 3) * (2 * STG_U * 4);
        const __half* a = Ap + kt * 32;
        const __half* b = Wp + kt * 32;
        CP_ASYNC16(dstA + sb,      a);
        CP_ASYNC16(dstA + sb + 16, a + 8);
        CP_ASYNC16(dstB + sb,      b);
        CP_ASYNC16(dstB + sb + 16, b + 8);
        CP_COMMIT();
    };

    float acc[4][4][4];
#pragma unroll
    for (int i = 0; i < 4; i++)
#pragma unroll
        for (int j = 0; j < 4; j++)
#pragma unroll
            for (int x = 0; x < 4; x++) acc[i][j][x] = 0.f;

    issue(0);
    issue(1);

    const int NKT = K / 32;   // 32
    for (int kt = 0; kt < NKT; kt++) {
        CP_WAIT(1);
        __syncthreads();

        const uint32_t sa = smbase + (kt % 3) * 2 * STG_U * 4;
        const uint32_t sb = sa + STG_U * 4;
#pragma unroll
        for (int s = 0; s < 2; s++) {
            const int g0 = s * 8;
            unsigned af[4][4], bf[4][2];
#pragma unroll
            for (int mf = 0; mf < 4; mf++) {
                const int rr = wm * 64 + mf * 16 + agrp_r + lrow;
                LDSM_X4(af[mf][0], af[mf][1], af[mf][2], af[mf][3],
                        sa + (rr * GST + g0 + agrp_c) * 4);
            }
#pragma unroll
            for (int np = 0; np < 2; np++) {
                const int rr = wn * 32 + (np * 2) * 8 + bgrp_r + lrow;
                LDSM_X4(bf[np*2][0], bf[np*2][1], bf[np*2+1][0], bf[np*2+1][1],
                        sb + (rr * GST + g0 + bgrp_c) * 4);
            }
#pragma unroll
            for (int mf = 0; mf < 4; mf++)
#pragma unroll
                for (int nf = 0; nf < 4; nf++)
                    MMA_FP16(acc[mf][nf], af[mf], bf[nf][0], bf[nf][1]);
        }
        if (kt + 2 < NKT) issue(kt + 2);
    }

    // epilogue
#pragma unroll
    for (int nf = 0; nf < 4; nf++) {
        const int col = n0 + wn * 32 + nf * 8 + (lane & 3) * 2;
        const float bv0 = bias[col], bv1 = bias[col + 1];
#pragma unroll
        for (int mf = 0; mf < 4; mf++) {
            const int row = m0 + wm * 64 + mf * 16 + (lane >> 2);
            float2 v0 = make_float2(acc[mf][nf][0] + bv0, acc[mf][nf][1] + bv1);
            float2 v1 = make_float2(acc[mf][nf][2] + bv0, acc[mf][nf][3] + bv1);
            if (!FUSED) {
                *(float2*)(C + (size_t)row * N + col)       = v0;
                *(float2*)(C + (size_t)(row + 8) * N + col) = v1;
            } else if (which < 2) {
                __half* P = which == 0 ? Qf : Kf;
                const int h = col >> 6, d = col & 63;
                const int bb0 = row >> 10, tt0 = row & 1023;
                const int bb1 = (row + 8) >> 10, tt1 = (row + 8) & 1023;
                const size_t o0 = ((((size_t)bb0 * H_ + h) * T_ + tt0) * DH) + d;
                const size_t o1 = ((((size_t)bb1 * H_ + h) * T_ + tt1) * DH) + d;
                *(__half2*)(P + o0) = __floats2half2_rn(v0.x, v0.y);
                *(__half2*)(P + o1) = __floats2half2_rn(v1.x, v1.y);
            } else {  // V half, transposed [B,H,D,T]
                const int h = col >> 6, d = col & 63;
                const int bb = row >> 10, tt = row & 1023;
                const size_t vb = (((size_t)bb * H_ + h) * DH + d) * T_ + tt;
                Vh[vb]          = __float2half(v0.x);
                Vh[vb + T_]     = __float2half(v0.y);
                Vh[vb + 8]      = __float2half(v1.x);
                Vh[vb + T_ + 8] = __float2half(v1.y);
            }
        }
    }
}

// ---------------------------------------------------------------------------
// Fused causal algebraic attention v6: PLAIN fp16 stage-1.
//   Stage1: S = Q @ K^T, fp16 k16 (16 MMA/tile)   [Q,K carry fp16-proj error
//           already; extra 2^-11 quantization is absorbed by normalization]
//   Stage2: O += (S*W) @ V, fp16 k16 (16 MMA/tile)
// K/V double-buffered + prefetched one iteration ahead; Q frags in regs.
// smem: 6 tiles -> 55808 B -> 3 CTA/SM.
// ---------------------------------------------------------------------------
#define PST 36
#define ATILE (64 * PST)
#define ATB   (ATILE * 4)

__global__ void __launch_bounds__(256, 3)
attn_v6(const __half* __restrict__ Qg, const __half* __restrict__ Kg,
        const __half* __restrict__ Vtg, const float* __restrict__ rel_bias,
        __half* __restrict__ out)
{
    extern __shared__ unsigned sm[];
    unsigned* Qh_s = sm;                    // tile 0
    unsigned* Kh_s = Qh_s + ATILE;          // tiles 1,2 (buf 0/1)
    unsigned* Vt_s = Kh_s + 2 * ATILE;      // tiles 3,4
    unsigned* Ws_s = Vt_s + 2 * ATILE;      // tile 5
    float* bh   = (float*)(Ws_s + ATILE);
    float* rsum = bh + 64;

    const int qt = 15 - (int)blockIdx.x;
    const int h  = blockIdx.y;
    const int b  = blockIdx.z;
    const int t  = threadIdx.x;
    const int lane = t & 31, warp = t >> 5;
    const int wm = warp >> 1, wn = warp & 1;
    const int q0 = qt * 64;
    const int bhx = b * H_ + h;

    const int lrow = lane & 7;
    const int agrp_r = ((lane >> 3) & 1) * 8;
    const int agrp_c = ((lane >> 4) & 1) * 4;
    const int bgrp_r = ((lane >> 4) & 1) * 8;
    const int bgrp_c = ((lane >> 3) & 1) * 4;

    const uint32_t qh_b = smem_u32(Qh_s);
    const uint32_t kh_b = smem_u32(Kh_s);
    const uint32_t vt_b = smem_u32(Vt_s), ws_b = smem_u32(Ws_s);

    const int r4  = t >> 2;
    const int cp8 = (t & 3) * 8;

    // view fp16 [.,64] rows as 32 u32 per row
    const unsigned* Qg32 = (const unsigned*)Qg + (size_t)bhx * T_ * 32;
    const unsigned* Kg32 = (const unsigned*)Kg + (size_t)bhx * T_ * 32;
    const __half*   Vbg  = Vtg + (size_t)bhx * DH * T_;

    auto issue = [&](int kt, int buf) {
        const int k0 = kt * 64;
        const size_t koff = (size_t)(k0 + r4) * 32 + cp8;
        const uint32_t kb = kh_b + buf * ATB + (r4 * PST + cp8) * 4;
        CP_ASYNC16(kb,      Kg32 + koff);
        CP_ASYNC16(kb + 16, Kg32 + koff + 4);
        const __half* vp = Vbg + (size_t)r4 * T_ + k0 + (t & 3) * 16;
        const uint32_t vb = vt_b + buf * ATB + (r4 * PST + cp8) * 4;
        CP_ASYNC16(vb,      vp);
        CP_ASYNC16(vb + 16, vp + 8);
        CP_COMMIT();
    };

    // prologue: Q (group), tile 0 (group)
    {
        const size_t qoff = (size_t)(q0 + r4) * 32 + cp8;
        CP_ASYNC16(qh_b + (r4 * PST + cp8) * 4,      Qg32 + qoff);
        CP_ASYNC16(qh_b + (r4 * PST + cp8) * 4 + 16, Qg32 + qoff + 4);
        CP_COMMIT();
    }
    issue(0, 0);
    if (t < 2 * MAXREL - 1) bh[t] = rel_bias[t * H_ + h];
    if (t < 64) rsum[t] = 0.f;

    CP_WAIT(1);
    __syncthreads();
    unsigned qf[4][4];
#pragma unroll
    for (int st = 0; st < 4; st++) {
        const int g0 = st * 8;
        const int rr = wm * 16 + agrp_r + lrow;
        LDSM_X4(qf[st][0], qf[st][1], qf[st][2], qf[st][3],
                qh_b + (rr * PST + g0 + agrp_c) * 4);
    }

    float oacc[4][4];
#pragma unroll
    for (int i = 0; i < 4; i++)
#pragma unroll
        for (int j = 0; j < 4; j++) oacc[i][j] = 0.f;
    float rp0 = 0.f, rp1 = 0.f;

    const int ar = wm * 16 + (lane >> 2);

    for (int kt = 0; kt <= qt; kt++) {
        const int buf = kt & 1;
        const int k0 = kt * 64;

        CP_WAIT(0);          // tile kt resident (issued a full iteration ago)
        __syncthreads();
        if (kt + 1 <= qt) issue(kt + 1, buf ^ 1);

        // Stage 1: S = Q @ K^T, plain fp16
        float s[4][4];
#pragma unroll
        for (int i = 0; i < 4; i++)
#pragma unroll
            for (int j = 0; j < 4; j++) s[i][j] = 0.f;

        const uint32_t khb = kh_b + buf * ATB;
#pragma unroll
        for (int st = 0; st < 4; st++) {
            const int g0 = st * 8;
            unsigned bf[4][2];
#pragma unroll
            for (int np = 0; np < 2; np++) {
                const int rr = wn * 32 + (np * 2) * 8 + bgrp_r + lrow;
                LDSM_X4(bf[np*2][0], bf[np*2][1], bf[np*2+1][0], bf[np*2+1][1],
                        khb + (rr * PST + g0 + bgrp_c) * 4);
            }
#pragma unroll
            for (int nf = 0; nf < 4; nf++)
                MMA_FP16(s[nf], qf[st], bf[nf][0], bf[nf][1]);
        }

        // Epilogue -> W (half, scaled) + rsum (unscaled, fp32)
        {
            const int qg0 = q0 + ar;
            const bool diag = (kt == qt);
#pragma unroll
            for (int nf = 0; nf < 4; nf++) {
                const int kg0 = k0 + wn * 32 + nf * 8 + (lane & 3) * 2;
                float w[4];
#pragma unroll
                for (int c = 0; c < 4; c++) {
                    const int qg = qg0 + (c >> 1) * 8;
                    const int kg = kg0 + (c & 1);
                    const int rel = kg - qg;
                    float wv = 0.f;
                    if (!diag || rel <= 0) {
                        const int u = max(rel + (MAXREL - 1), 0);
                        wv = fmaxf(fmaf(s[nf][c], 0.125f, bh[u]), 0.f) + 1e-6f;
                    }
                    w[c] = wv;
                }
                rp0 += w[0] + w[1];
                rp1 += w[2] + w[3];
                const int pc = wn * 16 + nf * 4 + (lane & 3);
                __half2 h0 = __floats2half2_rn(w[0] * WSCALE, w[1] * WSCALE);
                __half2 h1 = __floats2half2_rn(w[2] * WSCALE, w[3] * WSCALE);
                Ws_s[ar * PST + pc]       = *(unsigned*)&h0;
                Ws_s[(ar + 8) * PST + pc] = *(unsigned*)&h1;
            }
        }
        __syncthreads();

        // Stage 2: O += W @ V, fp16 k16
        const uint32_t vtb = vt_b + buf * ATB;
#pragma unroll
        for (int st = 0; st < 4; st++) {
            const int g0 = st * 8;
            unsigned a[4], bf[4][2];
            {
                const int rr = wm * 16 + agrp_r + lrow;
                LDSM_X4(a[0], a[1], a[2], a[3],
                        ws_b + (rr * PST + g0 + agrp_c) * 4);
            }
#pragma unroll
            for (int np = 0; np < 2; np++) {
                const int rr = wn * 32 + (np * 2) * 8 + bgrp_r + lrow;
                LDSM_X4(bf[np*2][0], bf[np*2][1], bf[np*2+1][0], bf[np*2+1][1],
                        vtb + (rr * PST + g0 + bgrp_c) * 4);
            }
#pragma unroll
            for (int nf = 0; nf < 4; nf++)
                MMA_FP16(oacc[nf], a, bf[nf][0], bf[nf][1]);
        }
    }

    rp0 += __shfl_xor_sync(0xffffffffu, rp0, 1);
    rp0 += __shfl_xor_sync(0xffffffffu, rp0, 2);
    rp1 += __shfl_xor_sync(0xffffffffu, rp1, 1);
    rp1 += __shfl_xor_sync(0xffffffffu, rp1, 2);
    if ((lane & 3) == 0) {
        atomicAdd(&rsum[ar], rp0);
        atomicAdd(&rsum[ar + 8], rp1);
    }
    __syncthreads();

    const float inv0 = WSCALE_INV / (rsum[ar] + 1e-6f);
    const float inv1 = WSCALE_INV / (rsum[ar + 8] + 1e-6f);
#pragma unroll
    for (int nf = 0; nf < 4; nf++) {
        const int d = wn * 32 + nf * 8 + (lane & 3) * 2;
        __half* dst0 = out + (size_t)(b * T_ + q0 + ar) * C_ + h * DH + d;
        __half* dst1 = out + (size_t)(b * T_ + q0 + ar + 8) * C_ + h * DH + d;
        __half2 h0 = __floats2half2_rn(oacc[nf][0] * inv0, oacc[nf][1] * inv0);
        __half2 h1 = __floats2half2_rn(oacc[nf][2] * inv1, oacc[nf][3] * inv1);
        *(__half2*)dst0 = h0;
        *(__half2*)dst1 = h1;
    }
}

#define ATTN_SMEM ((6 * ATILE + 128) * 4)   // 55808 B

// ---------------------------------------------------------------------------
extern "C" void kernel_launch(void* const* d_in, const int* in_sizes, int n_in,
                              void* d_out, int out_size)
{
    const float* x   = (const float*)d_in[0];
    const float* Wq  = (const float*)d_in[2];
    const float* bq  = (const float*)d_in[3];
    const float* Wk  = (const float*)d_in[4];
    const float* bk  = (const float*)d_in[5];
    const float* Wv  = (const float*)d_in[6];
    const float* bv  = (const float*)d_in[7];
    const float* Wo  = (const float*)d_in[8];
    const float* bo  = (const float*)d_in[9];
    const float* rel = (const float*)d_in[10];

    __half *x2, *w2q, *w2k, *w2v, *w2o, *ath, *qh, *kh, *vth;
    cudaGetSymbolAddress((void**)&x2,  g_x2);
    cudaGetSymbolAddress((void**)&w2q, g_w2q);
    cudaGetSymbolAddress((void**)&w2k, g_w2k);
    cudaGetSymbolAddress((void**)&w2v, g_w2v);
    cudaGetSymbolAddress((void**)&w2o, g_w2o);
    cudaGetSymbolAddress((void**)&ath, g_ath);
    cudaGetSymbolAddress((void**)&qh,  g_Qh);
    cudaGetSymbolAddress((void**)&kh,  g_Kh);
    cudaGetSymbolAddress((void**)&vth, g_Vth);

    static int configured = 0;
    if (!configured) {
        cudaFuncSetAttribute(attn_v6, cudaFuncAttributeMaxDynamicSharedMemorySize,
                             ATTN_SMEM);
        cudaFuncSetAttribute(gemm_h2<0>, cudaFuncAttributeMaxDynamicSharedMemorySize,
                             GEMM_SMEM);
        cudaFuncSetAttribute(gemm_h2<1>, cudaFuncAttributeMaxDynamicSharedMemorySize,
                             GEMM_SMEM);
        configured = 1;
    }

    const int NX = B_ * T_ * C_, NW = C_ * C_;
    cvt_all<<<dim3(NX / 2048, 5), 256>>>(Wq, w2q, Wk, w2k, Wv, w2v, Wo, w2o,
                                         x, x2, NW, NX);

    // Fused Q/K/V projections: ONE launch, 768 CTAs (grid 24 x 32)
    gemm_h2<1><<<dim3(24, 32), 256, GEMM_SMEM>>>(
        x2, w2q, w2k, w2v, bq, bk, bv, nullptr, qh, kh, vth);

    attn_v6<<<dim3(16, H_, B_), 256, ATTN_SMEM>>>(qh, kh, vth, rel, ath);

    gemm_h2<0><<<dim3(8, 32), 256, GEMM_SMEM>>>(
        ath, w2o, nullptr, nullptr, bo, nullptr, nullptr,
        (float*)d_out, nullptr, nullptr, nullptr);
}